// round 15
// baseline (speedup 1.0000x reference)
#include <cuda_runtime.h>
#include <cuda_bf16.h>
#include <math.h>
#include <stdint.h>

#define T   2048
#define D   1024
#define E   8
#define DFS 2048
#define DFE 512

// ---------------- scratch (device globals) ----------------------------------
__device__ __nv_bfloat16 d_xh[(size_t)T * D],     d_xl[(size_t)T * D];
__device__ __nv_bfloat16 d_sgwh[(size_t)DFS * D], d_sgwl[(size_t)DFS * D];
__device__ __nv_bfloat16 d_suwh[(size_t)DFS * D], d_suwl[(size_t)DFS * D];
__device__ __nv_bfloat16 d_sdwh[(size_t)D * DFS], d_sdwl[(size_t)D * DFS];
__device__ __nv_bfloat16 d_hsh[(size_t)T * DFS],  d_hsl[(size_t)T * DFS];
__device__ __nv_bfloat16 d_heh[(size_t)E * T * DFE], d_hel[(size_t)E * T * DFE];
__device__ __nv_bfloat16 d_gqb[(size_t)E * DFE * D];
__device__ __nv_bfloat16 d_uqb[(size_t)E * DFE * D];
__device__ __nv_bfloat16 d_dqb[(size_t)E * D * DFE];
__device__ float d_gsv[(size_t)T * DFS];
__device__ float d_gev[(size_t)E * T * DFE];
__device__ float d_shared[(size_t)T * D];
__device__ float d_eo[(size_t)E * T * D];
__device__ int   d_cnt[E];
__device__ int   d_toklist[E * T];
__device__ int   d_tok_e[T * 2];
__device__ int   d_tok_p[T * 2];
__device__ float d_tok_w[T * 2];

__device__ __forceinline__ float silu_f(float g) { return g / (1.f + expf(-g)); }

struct __align__(8) bf16x4 { __nv_bfloat162 a, b; };

// ---------------- primitives -------------------------------------------------
__device__ __forceinline__ uint32_t smem_u32(const void* p) {
    uint32_t a;
    asm("{ .reg .u64 t; cvta.to.shared.u64 t, %1; cvt.u32.u64 %0, t; }" : "=r"(a) : "l"(p));
    return a;
}
__device__ __forceinline__ void cpa16(uint32_t sa, const void* gp) {
    asm volatile("cp.async.cg.shared.global [%0], [%1], 16;" :: "r"(sa), "l"(gp));
}
__device__ __forceinline__ void ldm_x4(uint32_t& r0, uint32_t& r1, uint32_t& r2, uint32_t& r3,
                                       uint32_t addr) {
    asm volatile("ldmatrix.sync.aligned.m8n8.x4.shared.b16 {%0,%1,%2,%3}, [%4];"
                 : "=r"(r0), "=r"(r1), "=r"(r2), "=r"(r3) : "r"(addr));
}
__device__ __forceinline__ void mma_bf16(float* c, const uint32_t* a, const uint32_t* b) {
    asm volatile("mma.sync.aligned.m16n8k16.row.col.f32.bf16.bf16.f32 "
                 "{%0,%1,%2,%3}, {%4,%5,%6,%7}, {%8,%9}, {%0,%1,%2,%3};"
                 : "+f"(c[0]), "+f"(c[1]), "+f"(c[2]), "+f"(c[3])
                 : "r"(a[0]), "r"(a[1]), "r"(a[2]), "r"(a[3]), "r"(b[0]), "r"(b[1]));
}

// ---------------- router ----------------------------------------------------
__global__ void zero_counts_kernel() { if (threadIdx.x < E) d_cnt[threadIdx.x] = 0; }

__global__ void router_kernel(const float* __restrict__ x,
                              const float* __restrict__ rw,
                              const float* __restrict__ alpha) {
    int warp = (blockIdx.x * blockDim.x + threadIdx.x) >> 5;
    int lane = threadIdx.x & 31;
    if (warp >= T) return;
    const float* xr = x + (size_t)warp * D;
    float acc[E];
#pragma unroll
    for (int e = 0; e < E; e++) acc[e] = 0.f;
    for (int d = lane; d < D; d += 32) {
        float xv = xr[d];
#pragma unroll
        for (int e = 0; e < E; e++) acc[e] = fmaf(xv, rw[e * D + d], acc[e]);
    }
#pragma unroll
    for (int e = 0; e < E; e++)
#pragma unroll
        for (int o = 16; o > 0; o >>= 1) acc[e] += __shfl_xor_sync(0xffffffffu, acc[e], o);
    if (lane == 0) {
        int e0 = 0;
#pragma unroll
        for (int e = 1; e < E; e++) if (acc[e] > acc[e0]) e0 = e;
        int e1 = -1; float v1 = -1e30f;
#pragma unroll
        for (int e = 0; e < E; e++) { if (e == e0) continue; if (acc[e] > v1) { v1 = acc[e]; e1 = e; } }
        float ew = expf(v1 - acc[e0]);
        float inv = 1.f / (1.f + ew);
        float cw0 = inv * alpha[e0], cw1 = ew * inv * alpha[e1];
        int p0 = atomicAdd(&d_cnt[e0], 1);
        int p1 = atomicAdd(&d_cnt[e1], 1);
        d_toklist[e0 * T + p0] = warp;
        d_toklist[e1 * T + p1] = warp;
        d_tok_e[warp * 2 + 0] = e0; d_tok_p[warp * 2 + 0] = p0; d_tok_w[warp * 2 + 0] = cw0;
        d_tok_e[warp * 2 + 1] = e1; d_tok_p[warp * 2 + 1] = p1; d_tok_w[warp * 2 + 1] = cw1;
    }
}

// ---------------- prologue converters ---------------------------------------
__global__ void quant_to_bf16(const int* __restrict__ q, __nv_bfloat16* __restrict__ o, int n4) {
    int i = blockIdx.x * blockDim.x + threadIdx.x;
    if (i >= n4) return;
    int4 v = ((const int4*)q)[i];
    bf16x4 r;
    r.a = __halves2bfloat162(__float2bfloat16((float)v.x), __float2bfloat16((float)v.y));
    r.b = __halves2bfloat162(__float2bfloat16((float)v.z), __float2bfloat16((float)v.w));
    ((bf16x4*)o)[i] = r;
}

__global__ void split_f32(const float* __restrict__ src, __nv_bfloat16* __restrict__ hi,
                          __nv_bfloat16* __restrict__ lo, int n4) {
    int i = blockIdx.x * blockDim.x + threadIdx.x;
    if (i >= n4) return;
    float4 v = ((const float4*)src)[i];
    __nv_bfloat16 hx = __float2bfloat16(v.x), hy = __float2bfloat16(v.y);
    __nv_bfloat16 hz = __float2bfloat16(v.z), hw = __float2bfloat16(v.w);
    bf16x4 h, l;
    h.a = __halves2bfloat162(hx, hy); h.b = __halves2bfloat162(hz, hw);
    l.a = __halves2bfloat162(__float2bfloat16(v.x - __bfloat162float(hx)),
                             __float2bfloat16(v.y - __bfloat162float(hy)));
    l.b = __halves2bfloat162(__float2bfloat16(v.z - __bfloat162float(hz)),
                             __float2bfloat16(v.w - __bfloat162float(hw)));
    ((bf16x4*)hi)[i] = h;
    ((bf16x4*)lo)[i] = l;
}

#define LDA 40

// ============ M256 kernel: shared MLP (TERMS=3, AMODE=0) ======================
// CTA 256x128, 8 warps of 64x64, 3-stage cp.async, 1 sync/chunk.
// Stage layout (elems): Ah 256*LDA | Al 256*LDA | Bh 128*LDA | Bl 128*LDA
#define SSE (2 * 256 * LDA + 2 * 128 * LDA)   // 30720  (R14 FIX: was half)
#define OAH 0
#define OAL (256 * LDA)
#define OBH (512 * LDA)
#define OBL (512 * LDA + 128 * LDA)

template <int EPI>
__global__ __launch_bounds__(256, 1)
void hmma_gemm256(const __nv_bfloat16* __restrict__ Ah, const __nv_bfloat16* __restrict__ Al,
                  const __nv_bfloat16* __restrict__ Bh, const __nv_bfloat16* __restrict__ Bl,
                  const float* __restrict__ G,
                  float* __restrict__ Cf, __nv_bfloat16* __restrict__ Chi,
                  __nv_bfloat16* __restrict__ Clo, int N, int K) {
    extern __shared__ char smem[];
    const int row0 = blockIdx.y * 256, col0 = blockIdx.x * 128;
    const int tid = threadIdx.x, wid = tid >> 5, lane = tid & 31;
    const int warp_m = wid & 3, warp_n = wid >> 2;
    const int g = lane >> 2, tg = lane & 3;

    __nv_bfloat16* tp = (__nv_bfloat16*)smem;
    const uint32_t tb = smem_u32(tp);

    const int lr = tid >> 2, seg = tid & 3;
    const size_t a0 = (size_t)(row0 + lr) * K + seg * 8;
    const size_t a1 = (size_t)(row0 + lr + 64) * K + seg * 8;
    const size_t a2 = (size_t)(row0 + lr + 128) * K + seg * 8;
    const size_t a3 = (size_t)(row0 + lr + 192) * K + seg * 8;
    const size_t b0 = (size_t)(col0 + lr) * K + seg * 8;
    const size_t b1 = (size_t)(col0 + lr + 64) * K + seg * 8;
    const uint32_t sA0 = (uint32_t)((lr)       * LDA + seg * 8) * 2;
    const uint32_t sA1 = (uint32_t)((lr + 64)  * LDA + seg * 8) * 2;
    const uint32_t sA2 = (uint32_t)((lr + 128) * LDA + seg * 8) * 2;
    const uint32_t sA3 = (uint32_t)((lr + 192) * LDA + seg * 8) * 2;

#define ISSUE256(cc, ss) do {                                                \
        const int k0_ = (cc) << 5;                                           \
        const uint32_t sb_ = tb + (uint32_t)((ss) * SSE) * 2;                \
        cpa16(sb_ + sA0,              Ah + a0 + k0_);                        \
        cpa16(sb_ + sA1,              Ah + a1 + k0_);                        \
        cpa16(sb_ + sA2,              Ah + a2 + k0_);                        \
        cpa16(sb_ + sA3,              Ah + a3 + k0_);                        \
        cpa16(sb_ + OAL * 2 + sA0,    Al + a0 + k0_);                        \
        cpa16(sb_ + OAL * 2 + sA1,    Al + a1 + k0_);                        \
        cpa16(sb_ + OAL * 2 + sA2,    Al + a2 + k0_);                        \
        cpa16(sb_ + OAL * 2 + sA3,    Al + a3 + k0_);                        \
        cpa16(sb_ + OBH * 2 + sA0,    Bh + b0 + k0_);                        \
        cpa16(sb_ + OBH * 2 + sA1,    Bh + b1 + k0_);                        \
        cpa16(sb_ + OBL * 2 + sA0,    Bl + b0 + k0_);                        \
        cpa16(sb_ + OBL * 2 + sA1,    Bl + b1 + k0_);                        \
        asm volatile("cp.async.commit_group;" ::: "memory");                 \
    } while (0)

    float acc[4][8][4];
#pragma unroll
    for (int i = 0; i < 4; i++)
#pragma unroll
        for (int j = 0; j < 8; j++)
#pragma unroll
            for (int k = 0; k < 4; k++) acc[i][j][k] = 0.f;

    const uint32_t a_lm = (uint32_t)((warp_m * 64 + (lane & 15)) * LDA + (lane >> 4) * 8) * 2;
    const int brr = ((lane >> 4) << 3) + (lane & 7);
    const uint32_t bcol = (uint32_t)(((lane >> 3) & 1) * 8) * 2;
    uint32_t b_lm[4];
#pragma unroll
    for (int q = 0; q < 4; q++)
        b_lm[q] = (uint32_t)((warp_n * 64 + q * 16 + brr) * LDA) * 2 + bcol;

    const int nch = K >> 5;
    ISSUE256(0, 0);
    ISSUE256(1, 1);

    for (int c = 0; c < nch; c++) {
        // R14 FIX: on the final chunk nothing is committed after it, so we
        // must drain fully (wait_group 0); wait_group 1 would race the last tile.
        if (c + 1 < nch) asm volatile("cp.async.wait_group 1;" ::: "memory");
        else             asm volatile("cp.async.wait_group 0;" ::: "memory");
        __syncthreads();
        if (c + 2 < nch) ISSUE256(c + 2, (c + 2) % 3);

        const uint32_t uS = tb + (uint32_t)((c % 3) * SSE) * 2;
        const uint32_t uAh = uS, uAl = uS + OAL * 2, uBh = uS + OBH * 2, uBl = uS + OBL * 2;

#pragma unroll
        for (int ks = 0; ks < 2; ks++) {
            const uint32_t kofs = (uint32_t)(ks * 16) * 2;
            uint32_t bh[8][2], bl[8][2];
#pragma unroll
            for (int q = 0; q < 4; q++)
                ldm_x4(bh[2 * q][0], bh[2 * q][1], bh[2 * q + 1][0], bh[2 * q + 1][1],
                       uBh + b_lm[q] + kofs);
#pragma unroll
            for (int q = 0; q < 4; q++)
                ldm_x4(bl[2 * q][0], bl[2 * q][1], bl[2 * q + 1][0], bl[2 * q + 1][1],
                       uBl + b_lm[q] + kofs);
#pragma unroll
            for (int am = 0; am < 4; am++) {
                uint32_t a[4];
                ldm_x4(a[0], a[1], a[2], a[3],
                       uAh + a_lm + kofs + (uint32_t)(am * 16 * LDA) * 2);
#pragma unroll
                for (int bn = 0; bn < 8; bn++) mma_bf16(acc[am][bn], a, bh[bn]);
#pragma unroll
                for (int bn = 0; bn < 8; bn++) mma_bf16(acc[am][bn], a, bl[bn]);
            }
#pragma unroll
            for (int am = 0; am < 4; am++) {
                uint32_t a[4];
                ldm_x4(a[0], a[1], a[2], a[3],
                       uAl + a_lm + kofs + (uint32_t)(am * 16 * LDA) * 2);
#pragma unroll
                for (int bn = 0; bn < 8; bn++) mma_bf16(acc[am][bn], a, bh[bn]);
            }
        }
    }
#undef ISSUE256

    // ---- epilogue ----
#pragma unroll
    for (int am = 0; am < 4; am++) {
#pragma unroll
        for (int half = 0; half < 2; half++) {
            const int pos = row0 + warp_m * 64 + am * 16 + g + half * 8;
            const size_t rbase = (size_t)pos * (size_t)N;
#pragma unroll
            for (int bn = 0; bn < 8; bn++) {
                const int cc = col0 + warp_n * 64 + bn * 8 + tg * 2;
                float v0 = acc[am][bn][half * 2 + 0];
                float v1 = acc[am][bn][half * 2 + 1];
                if (EPI == 1) {
                    const float2 g2 = *(const float2*)(G + rbase + cc);
                    v0 = silu_f(g2.x) * v0; v1 = silu_f(g2.y) * v1;
                    __nv_bfloat16 h0 = __float2bfloat16(v0), h1 = __float2bfloat16(v1);
                    *(__nv_bfloat162*)(Chi + rbase + cc) = __halves2bfloat162(h0, h1);
                    *(__nv_bfloat162*)(Clo + rbase + cc) = __halves2bfloat162(
                        __float2bfloat16(v0 - __bfloat162float(h0)),
                        __float2bfloat16(v1 - __bfloat162float(h1)));
                } else {
                    *(float2*)(Cf + rbase + cc) = make_float2(v0, v1);
                }
            }
        }
    }
}

// ============ M128 kernel: experts (TERMS=2) — unchanged from R13 =============
template <int AMODE, int EPI>
__global__ __launch_bounds__(256)
void hmma_gemm(const __nv_bfloat16* __restrict__ Ah, const __nv_bfloat16* __restrict__ Al,
               const __nv_bfloat16* __restrict__ Bh,
               const float* __restrict__ scl, const float* __restrict__ G,
               float* __restrict__ Cf, __nv_bfloat16* __restrict__ Chi,
               __nv_bfloat16* __restrict__ Clo, int N, int K) {
    constexpr int NT = 3;
    constexpr int TILE_E = 128 * LDA;
    extern __shared__ char smem[];
    const int e = blockIdx.z;
    const int cnt = d_cnt[e];
    if ((int)blockIdx.y * 128 >= cnt) return;
    const int row0 = blockIdx.y * 128, col0 = blockIdx.x * 128;
    const int tid = threadIdx.x, wid = tid >> 5, lane = tid & 31;
    const int warp_m = wid >> 2, warp_n = wid & 3;
    const int g = lane >> 2, tg = lane & 3;

    const size_t b_base = (size_t)e * (size_t)N * (size_t)K;

    int* s_arow = (int*)smem;
    __nv_bfloat16* tp = (__nv_bfloat16*)(smem + 512);
    const uint32_t tb = smem_u32(tp);

    if (tid < 128) {
        int pos = row0 + tid;
        if (pos >= cnt) pos = cnt - 1;
        if (pos < 0) pos = 0;
        s_arow[tid] = (AMODE == 1) ? d_toklist[e * T + pos] : (e * T + pos);
    }
    __syncthreads();

    const int lr0 = tid >> 2, seg = tid & 3;
    const size_t aoff0 = (size_t)s_arow[lr0] * K + seg * 8;
    const size_t aoff1 = (size_t)s_arow[lr0 + 64] * K + seg * 8;
    const size_t boff0g = b_base + (size_t)(col0 + lr0) * K + seg * 8;
    const size_t boff1g = b_base + (size_t)(col0 + lr0 + 64) * K + seg * 8;
    const uint32_t so0 = (uint32_t)(lr0 * LDA + seg * 8) * 2;
    const uint32_t so1 = (uint32_t)((lr0 + 64) * LDA + seg * 8) * 2;

#define ISSUE_CHUNK(cc, ss) do {                                             \
        const int k0_ = (cc) << 5;                                           \
        const uint32_t sb_ = tb + (uint32_t)((ss) * NT * TILE_E) * 2;        \
        cpa16(sb_ + so0,              Ah + aoff0 + k0_);                     \
        cpa16(sb_ + so1,              Ah + aoff1 + k0_);                     \
        cpa16(sb_ + TILE_E * 2 + so0, Al + aoff0 + k0_);                     \
        cpa16(sb_ + TILE_E * 2 + so1, Al + aoff1 + k0_);                     \
        cpa16(sb_ + TILE_E * 4 + so0, Bh + boff0g + k0_);                    \
        cpa16(sb_ + TILE_E * 4 + so1, Bh + boff1g + k0_);                    \
        asm volatile("cp.async.commit_group;" ::: "memory");                 \
    } while (0)

    float acc[4][4][4];
#pragma unroll
    for (int i = 0; i < 4; i++)
#pragma unroll
        for (int j = 0; j < 4; j++)
#pragma unroll
            for (int k = 0; k < 4; k++) acc[i][j][k] = 0.f;

    const uint32_t a_lm = (uint32_t)((warp_m * 64 + (lane & 15)) * LDA + (lane >> 4) * 8) * 2;
    const int brow = warp_n * 32 + ((lane >> 4) << 3) + (lane & 7);
    const uint32_t b_lm0 = (uint32_t)(brow * LDA + ((lane >> 3) & 1) * 8) * 2;
    const uint32_t b_lm1 = (uint32_t)((brow + 16) * LDA + ((lane >> 3) & 1) * 8) * 2;

    const int nch = K >> 5;
    ISSUE_CHUNK(0, 0);

    for (int c = 0; c < nch; c++) {
        const int cur = c & 1;
        if (c + 1 < nch) {
            ISSUE_CHUNK(c + 1, cur ^ 1);
            asm volatile("cp.async.wait_group 1;" ::: "memory");
        } else {
            asm volatile("cp.async.wait_group 0;" ::: "memory");
        }
        __syncthreads();

        const uint32_t uAh = tb + (uint32_t)((cur * NT + 0) * TILE_E) * 2;
        const uint32_t uAl = tb + (uint32_t)((cur * NT + 1) * TILE_E) * 2;
        const uint32_t uBh = tb + (uint32_t)((cur * NT + 2) * TILE_E) * 2;

#pragma unroll
        for (int ks = 0; ks < 2; ks++) {
            const uint32_t kofs = (uint32_t)(ks * 16) * 2;
            uint32_t bh[4][2];
            ldm_x4(bh[0][0], bh[0][1], bh[1][0], bh[1][1], uBh + b_lm0 + kofs);
            ldm_x4(bh[2][0], bh[2][1], bh[3][0], bh[3][1], uBh + b_lm1 + kofs);
#pragma unroll
            for (int am = 0; am < 4; am++) {
                uint32_t a[4];
                ldm_x4(a[0], a[1], a[2], a[3],
                       uAh + a_lm + kofs + (uint32_t)(am * 16 * LDA) * 2);
#pragma unroll
                for (int bn = 0; bn < 4; bn++) mma_bf16(acc[am][bn], a, bh[bn]);
            }
#pragma unroll
            for (int am = 0; am < 4; am++) {
                uint32_t a[4];
                ldm_x4(a[0], a[1], a[2], a[3],
                       uAl + a_lm + kofs + (uint32_t)(am * 16 * LDA) * 2);
#pragma unroll
                for (int bn = 0; bn < 4; bn++) mma_bf16(acc[am][bn], a, bh[bn]);
            }
        }
        __syncthreads();
    }
#undef ISSUE_CHUNK

#pragma unroll
    for (int am = 0; am < 4; am++) {
#pragma unroll
        for (int half = 0; half < 2; half++) {
            const int pos = row0 + warp_m * 64 + am * 16 + g + half * 8;
            if (pos >= cnt) continue;
            const size_t rbase = ((size_t)e * T + pos) * (size_t)N;
#pragma unroll
            for (int bn = 0; bn < 4; bn++) {
                const int cc = col0 + warp_n * 32 + bn * 8 + tg * 2;
                float v0 = acc[am][bn][half * 2 + 0];
                float v1 = acc[am][bn][half * 2 + 1];
                const float2 s2 = *(const float2*)(scl + (size_t)e * N + cc);
                v0 *= s2.x; v1 *= s2.y;
                if (EPI == 3) {
                    const float2 g2 = *(const float2*)(G + rbase + cc);
                    v0 = silu_f(g2.x) * v0; v1 = silu_f(g2.y) * v1;
                    __nv_bfloat16 h0 = __float2bfloat16(v0), h1 = __float2bfloat16(v1);
                    *(__nv_bfloat162*)(Chi + rbase + cc) = __halves2bfloat162(h0, h1);
                    *(__nv_bfloat162*)(Clo + rbase + cc) = __halves2bfloat162(
                        __float2bfloat16(v0 - __bfloat162float(h0)),
                        __float2bfloat16(v1 - __bfloat162float(h1)));
                } else {
                    *(float2*)(Cf + rbase + cc) = make_float2(v0, v1);
                }
            }
        }
    }
}

// ---------------- final combine ---------------------------------------------
__global__ void combine_kernel(float* __restrict__ out) {
    int idx = blockIdx.x * blockDim.x + threadIdx.x;
    if (idx >= T * D / 4) return;
    int t = idx / (D / 4), d4 = idx % (D / 4);
    float cw0 = d_tok_w[t * 2 + 0], cw1 = d_tok_w[t * 2 + 1];
    int e0 = d_tok_e[t * 2 + 0], e1 = d_tok_e[t * 2 + 1];
    int p0 = d_tok_p[t * 2 + 0], p1 = d_tok_p[t * 2 + 1];
    float s = 1.f - cw0 - cw1;
    float4 a = ((const float4*)(d_shared + (size_t)t * D))[d4];
    float4 b = ((const float4*)(d_eo + ((size_t)e0 * T + p0) * D))[d4];
    float4 c = ((const float4*)(d_eo + ((size_t)e1 * T + p1) * D))[d4];
    float4 r;
    r.x = s * a.x + cw0 * b.x + cw1 * c.x;
    r.y = s * a.y + cw0 * b.y + cw1 * c.y;
    r.z = s * a.z + cw0 * b.z + cw1 * c.z;
    r.w = s * a.w + cw0 * b.w + cw1 * c.w;
    ((float4*)out)[(size_t)t * (D / 4) + d4] = r;
}

// ---------------- launch ----------------------------------------------------
#define SMEM256 (3 * SSE * 2)                 // 184320
#define SMEM2   (512 + 2 * 3 * 128 * LDA * 2) // 61952

extern "C" void kernel_launch(void* const* d_in, const int* in_sizes, int n_in,
                              void* d_out, int out_size) {
    const float *x, *rw, *sgw, *suw, *sdw, *gsc, *usc, *dsc, *alpha;
    const int *gq, *uq, *dq;
    bool dict_order = (n_in >= 12 && in_sizes[0] == T * D && in_sizes[1] == E * D &&
                       in_sizes[5] == E * DFE && in_sizes[8] == E);
    if (dict_order) {
        x = (const float*)d_in[0];  rw = (const float*)d_in[1];
        sgw = (const float*)d_in[2]; suw = (const float*)d_in[3];
        sdw = (const float*)d_in[4]; gsc = (const float*)d_in[5];
        usc = (const float*)d_in[6]; dsc = (const float*)d_in[7];
        alpha = (const float*)d_in[8];
        gq = (const int*)d_in[9]; uq = (const int*)d_in[10]; dq = (const int*)d_in[11];
    } else {
        alpha = (const float*)d_in[0];
        dq = (const int*)d_in[1];  dsc = (const float*)d_in[2];
        gq = (const int*)d_in[3];  gsc = (const float*)d_in[4];
        rw = (const float*)d_in[5];
        sdw = (const float*)d_in[6]; sgw = (const float*)d_in[7]; suw = (const float*)d_in[8];
        int o = (n_in >= 13 && in_sizes[9] == 1) ? 1 : 0;
        uq = (const int*)d_in[9 + o]; usc = (const float*)d_in[10 + o];
        x = (const float*)d_in[11 + o];
    }
    float* out = (float*)d_out;

    __nv_bfloat16 *p_xh, *p_xl, *p_sgwh, *p_sgwl, *p_suwh, *p_suwl, *p_sdwh, *p_sdwl;
    __nv_bfloat16 *p_hsh, *p_hsl, *p_heh, *p_hel, *p_gqb, *p_uqb, *p_dqb;
    float *p_gsv, *p_gev, *p_shared, *p_eo;
    cudaGetSymbolAddress((void**)&p_xh, d_xh);     cudaGetSymbolAddress((void**)&p_xl, d_xl);
    cudaGetSymbolAddress((void**)&p_sgwh, d_sgwh); cudaGetSymbolAddress((void**)&p_sgwl, d_sgwl);
    cudaGetSymbolAddress((void**)&p_suwh, d_suwh); cudaGetSymbolAddress((void**)&p_suwl, d_suwl);
    cudaGetSymbolAddress((void**)&p_sdwh, d_sdwh); cudaGetSymbolAddress((void**)&p_sdwl, d_sdwl);
    cudaGetSymbolAddress((void**)&p_hsh, d_hsh);   cudaGetSymbolAddress((void**)&p_hsl, d_hsl);
    cudaGetSymbolAddress((void**)&p_heh, d_heh);   cudaGetSymbolAddress((void**)&p_hel, d_hel);
    cudaGetSymbolAddress((void**)&p_gqb, d_gqb);   cudaGetSymbolAddress((void**)&p_uqb, d_uqb);
    cudaGetSymbolAddress((void**)&p_dqb, d_dqb);
    cudaGetSymbolAddress((void**)&p_gsv, d_gsv);   cudaGetSymbolAddress((void**)&p_gev, d_gev);
    cudaGetSymbolAddress((void**)&p_shared, d_shared);
    cudaGetSymbolAddress((void**)&p_eo, d_eo);

    cudaFuncSetAttribute(hmma_gemm256<0>, cudaFuncAttributeMaxDynamicSharedMemorySize, SMEM256);
    cudaFuncSetAttribute(hmma_gemm256<1>, cudaFuncAttributeMaxDynamicSharedMemorySize, SMEM256);
    cudaFuncSetAttribute(hmma_gemm<1, 2>, cudaFuncAttributeMaxDynamicSharedMemorySize, SMEM2);
    cudaFuncSetAttribute(hmma_gemm<1, 3>, cudaFuncAttributeMaxDynamicSharedMemorySize, SMEM2);
    cudaFuncSetAttribute(hmma_gemm<2, 2>, cudaFuncAttributeMaxDynamicSharedMemorySize, SMEM2);

    zero_counts_kernel<<<1, 32>>>();
    router_kernel<<<T / 8, 256>>>(x, rw, alpha);

    split_f32<<<(T * D / 4 + 255) / 256, 256>>>(x, p_xh, p_xl, T * D / 4);
    split_f32<<<(DFS * D / 4 + 255) / 256, 256>>>(sgw, p_sgwh, p_sgwl, DFS * D / 4);
    split_f32<<<(DFS * D / 4 + 255) / 256, 256>>>(suw, p_suwh, p_suwl, DFS * D / 4);
    split_f32<<<(D * DFS / 4 + 255) / 256, 256>>>(sdw, p_sdwh, p_sdwl, D * DFS / 4);
    {
        int n4 = E * DFE * D / 4;
        quant_to_bf16<<<(n4 + 255) / 256, 256>>>(gq, p_gqb, n4);
        quant_to_bf16<<<(n4 + 255) / 256, 256>>>(uq, p_uqb, n4);
        quant_to_bf16<<<(n4 + 255) / 256, 256>>>(dq, p_dqb, n4);
    }

    // shared MLP (3-term, M256 tiles)
    hmma_gemm256<0><<<dim3(DFS / 128, T / 256), 256, SMEM256>>>(
        p_xh, p_xl, p_sgwh, p_sgwl, nullptr, p_gsv, nullptr, nullptr, DFS, D);
    hmma_gemm256<1><<<dim3(DFS / 128, T / 256), 256, SMEM256>>>(
        p_xh, p_xl, p_suwh, p_suwl, p_gsv, nullptr, p_hsh, p_hsl, DFS, D);
    hmma_gemm256<0><<<dim3(D / 128, T / 256), 256, SMEM256>>>(
        p_hsh, p_hsl, p_sdwh, p_sdwl, nullptr, p_shared, nullptr, nullptr, D, DFS);

    // routed experts (2-term, M128 tiles — unchanged)
    hmma_gemm<1, 2><<<dim3(DFE / 128, T / 128, E), 256, SMEM2>>>(
        p_xh, p_xl, p_gqb, gsc, nullptr, p_gev, nullptr, nullptr, DFE, D);
    hmma_gemm<1, 3><<<dim3(DFE / 128, T / 128, E), 256, SMEM2>>>(
        p_xh, p_xl, p_uqb, usc, p_gev, nullptr, p_heh, p_hel, DFE, D);
    hmma_gemm<2, 2><<<dim3(D / 128, T / 128, E), 256, SMEM2>>>(
        p_heh, p_hel, p_dqb, dsc, nullptr, p_eo, nullptr, nullptr, D, DFE);

    combine_kernel<<<(T * D / 4 + 255) / 256, 256>>>(out);
}

// round 16
// speedup vs baseline: 1.1666x; 1.1666x over previous
#include <cuda_runtime.h>
#include <cuda_bf16.h>
#include <math.h>
#include <stdint.h>

#define T   2048
#define D   1024
#define E   8
#define DFS 2048
#define DFE 512

// ---------------- scratch (device globals) ----------------------------------
__device__ __nv_bfloat16 d_xh[(size_t)T * D],     d_xl[(size_t)T * D];
__device__ __nv_bfloat16 d_sgwh[(size_t)DFS * D], d_sgwl[(size_t)DFS * D];
__device__ __nv_bfloat16 d_suwh[(size_t)DFS * D], d_suwl[(size_t)DFS * D];
__device__ __nv_bfloat16 d_sdwh[(size_t)D * DFS], d_sdwl[(size_t)D * DFS];
__device__ __nv_bfloat16 d_hsh[(size_t)T * DFS],  d_hsl[(size_t)T * DFS];
__device__ __nv_bfloat16 d_heh[(size_t)E * T * DFE], d_hel[(size_t)E * T * DFE];
__device__ __nv_bfloat16 d_gqb[(size_t)E * DFE * D];
__device__ __nv_bfloat16 d_uqb[(size_t)E * DFE * D];
__device__ __nv_bfloat16 d_dqb[(size_t)E * D * DFE];
__device__ float d_gsv[(size_t)T * DFS];
__device__ float d_gev[(size_t)E * T * DFE];
__device__ float d_shared[(size_t)T * D];
__device__ float d_eo[(size_t)E * T * D];
__device__ int   d_cnt[E];
__device__ int   d_toklist[E * T];
__device__ int   d_tok_e[T * 2];
__device__ int   d_tok_p[T * 2];
__device__ float d_tok_w[T * 2];

__device__ __forceinline__ float silu_f(float g) { return g / (1.f + expf(-g)); }

struct __align__(8) bf16x4 { __nv_bfloat162 a, b; };

// ---------------- primitives -------------------------------------------------
__device__ __forceinline__ uint32_t smem_u32(const void* p) {
    uint32_t a;
    asm("{ .reg .u64 t; cvta.to.shared.u64 t, %1; cvt.u32.u64 %0, t; }" : "=r"(a) : "l"(p));
    return a;
}
__device__ __forceinline__ void cpa16(uint32_t sa, const void* gp) {
    asm volatile("cp.async.cg.shared.global [%0], [%1], 16;" :: "r"(sa), "l"(gp));
}
__device__ __forceinline__ void ldm_x4(uint32_t& r0, uint32_t& r1, uint32_t& r2, uint32_t& r3,
                                       uint32_t addr) {
    asm volatile("ldmatrix.sync.aligned.m8n8.x4.shared.b16 {%0,%1,%2,%3}, [%4];"
                 : "=r"(r0), "=r"(r1), "=r"(r2), "=r"(r3) : "r"(addr));
}
__device__ __forceinline__ void mma_bf16(float* c, const uint32_t* a, const uint32_t* b) {
    asm volatile("mma.sync.aligned.m16n8k16.row.col.f32.bf16.bf16.f32 "
                 "{%0,%1,%2,%3}, {%4,%5,%6,%7}, {%8,%9}, {%0,%1,%2,%3};"
                 : "+f"(c[0]), "+f"(c[1]), "+f"(c[2]), "+f"(c[3])
                 : "r"(a[0]), "r"(a[1]), "r"(a[2]), "r"(a[3]), "r"(b[0]), "r"(b[1]));
}

// ---------------- router ----------------------------------------------------
__global__ void router_kernel(const float* __restrict__ x,
                              const float* __restrict__ rw,
                              const float* __restrict__ alpha) {
    int warp = (blockIdx.x * blockDim.x + threadIdx.x) >> 5;
    int lane = threadIdx.x & 31;
    if (warp >= T) return;
    const float* xr = x + (size_t)warp * D;
    float acc[E];
#pragma unroll
    for (int e = 0; e < E; e++) acc[e] = 0.f;
    for (int d = lane; d < D; d += 32) {
        float xv = xr[d];
#pragma unroll
        for (int e = 0; e < E; e++) acc[e] = fmaf(xv, rw[e * D + d], acc[e]);
    }
#pragma unroll
    for (int e = 0; e < E; e++)
#pragma unroll
        for (int o = 16; o > 0; o >>= 1) acc[e] += __shfl_xor_sync(0xffffffffu, acc[e], o);
    if (lane == 0) {
        int e0 = 0;
#pragma unroll
        for (int e = 1; e < E; e++) if (acc[e] > acc[e0]) e0 = e;
        int e1 = -1; float v1 = -1e30f;
#pragma unroll
        for (int e = 0; e < E; e++) { if (e == e0) continue; if (acc[e] > v1) { v1 = acc[e]; e1 = e; } }
        float ew = expf(v1 - acc[e0]);
        float inv = 1.f / (1.f + ew);
        float cw0 = inv * alpha[e0], cw1 = ew * inv * alpha[e1];
        int p0 = atomicAdd(&d_cnt[e0], 1);
        int p1 = atomicAdd(&d_cnt[e1], 1);
        d_toklist[e0 * T + p0] = warp;
        d_toklist[e1 * T + p1] = warp;
        d_tok_e[warp * 2 + 0] = e0; d_tok_p[warp * 2 + 0] = p0; d_tok_w[warp * 2 + 0] = cw0;
        d_tok_e[warp * 2 + 1] = e1; d_tok_p[warp * 2 + 1] = p1; d_tok_w[warp * 2 + 1] = cw1;
    }
}

// ---------------- fused prologue: zero counts + all splits + all quants ------
// Region map (float4/int4 units):
//   [0,S)      split x        S = T*D/4
//   [S,2S)     split sh_gate
//   [2S,3S)    split sh_up
//   [3S,4S)    split sh_down
//   [4S,4S+Q)  quant gate     Q = E*DFE*D/4
//   [..+Q)     quant up
//   [..+Q)     quant down
#define PS (T * D / 4)
#define PQ (E * DFE * D / 4)
#define PTOT (4 * PS + 3 * PQ)

__device__ __forceinline__ void split_one(const float* __restrict__ src,
                                          __nv_bfloat16* __restrict__ hi,
                                          __nv_bfloat16* __restrict__ lo, int i) {
    float4 v = ((const float4*)src)[i];
    __nv_bfloat16 hx = __float2bfloat16(v.x), hy = __float2bfloat16(v.y);
    __nv_bfloat16 hz = __float2bfloat16(v.z), hw = __float2bfloat16(v.w);
    bf16x4 h, l;
    h.a = __halves2bfloat162(hx, hy); h.b = __halves2bfloat162(hz, hw);
    l.a = __halves2bfloat162(__float2bfloat16(v.x - __bfloat162float(hx)),
                             __float2bfloat16(v.y - __bfloat162float(hy)));
    l.b = __halves2bfloat162(__float2bfloat16(v.z - __bfloat162float(hz)),
                             __float2bfloat16(v.w - __bfloat162float(hw)));
    ((bf16x4*)hi)[i] = h;
    ((bf16x4*)lo)[i] = l;
}
__device__ __forceinline__ void quant_one(const int* __restrict__ q,
                                          __nv_bfloat16* __restrict__ o, int i) {
    int4 v = ((const int4*)q)[i];
    bf16x4 r;
    r.a = __halves2bfloat162(__float2bfloat16((float)v.x), __float2bfloat16((float)v.y));
    r.b = __halves2bfloat162(__float2bfloat16((float)v.z), __float2bfloat16((float)v.w));
    ((bf16x4*)o)[i] = r;
}

__global__ void prologue_kernel(const float* __restrict__ x,
                                const float* __restrict__ sgw,
                                const float* __restrict__ suw,
                                const float* __restrict__ sdw,
                                const int* __restrict__ gq,
                                const int* __restrict__ uq,
                                const int* __restrict__ dq) {
    int i = blockIdx.x * blockDim.x + threadIdx.x;
    if (i < E) d_cnt[i] = 0;
    if (i >= PTOT) return;
    if (i < 4 * PS) {
        int r = i >> 19;            // PS = 524288 = 2^19
        int j = i & (PS - 1);
        if (r == 0)      split_one(x,   d_xh,   d_xl,   j);
        else if (r == 1) split_one(sgw, d_sgwh, d_sgwl, j);
        else if (r == 2) split_one(suw, d_suwh, d_suwl, j);
        else             split_one(sdw, d_sdwh, d_sdwl, j);
    } else {
        int k = i - 4 * PS;
        int r = k >> 20;            // PQ = 1048576 = 2^20
        int j = k & (PQ - 1);
        if (r == 0)      quant_one(gq, d_gqb, j);
        else if (r == 1) quant_one(uq, d_uqb, j);
        else             quant_one(dq, d_dqb, j);
    }
}

#define LDA 40

// ============ M128 GEMM (R13-proven): ldmatrix + 2-stage cp.async ============
// TERMS: 3 = Ah*Bh + Al*Bh + Ah*Bl; 2 = Ah*B + Al*B (B exact bf16).
// AMODE: 0 plain rows; 1 gather toklist; 2 expert-contiguous rows.
// EPI: 0 fp32 | 1 silu(G)*v -> hi/lo | 2 v*scl -> fp32 | 3 silu(G)*(v*scl) -> hi/lo
template <int TERMS, int AMODE, int EPI>
__global__ __launch_bounds__(256)
void hmma_gemm(const __nv_bfloat16* __restrict__ Ah, const __nv_bfloat16* __restrict__ Al,
               const __nv_bfloat16* __restrict__ Bh, const __nv_bfloat16* __restrict__ Bl,
               const float* __restrict__ scl, const float* __restrict__ G,
               float* __restrict__ Cf, __nv_bfloat16* __restrict__ Chi,
               __nv_bfloat16* __restrict__ Clo, int N, int K) {
    constexpr int NT = (TERMS == 3) ? 4 : 3;
    constexpr int TILE_E = 128 * LDA;
    extern __shared__ char smem[];
    const int e = (AMODE ? blockIdx.z : 0);
    int cnt = T;
    if (AMODE) { cnt = d_cnt[e]; if ((int)blockIdx.y * 128 >= cnt) return; }
    const int row0 = blockIdx.y * 128, col0 = blockIdx.x * 128;
    const int tid = threadIdx.x, wid = tid >> 5, lane = tid & 31;
    const int warp_m = wid >> 2, warp_n = wid & 3;
    const int g = lane >> 2, tg = lane & 3;

    const size_t b_base = (size_t)e * (size_t)N * (size_t)K;

    int* s_arow = (int*)smem;
    __nv_bfloat16* tp = (__nv_bfloat16*)(smem + 512);
    const uint32_t tb = smem_u32(tp);

    if (tid < 128) {
        int pos = row0 + tid;
        if (pos >= cnt) pos = cnt - 1;
        if (pos < 0) pos = 0;
        int grow;
        if (AMODE == 1)      grow = d_toklist[e * T + pos];
        else if (AMODE == 2) grow = e * T + pos;
        else                 grow = pos;
        s_arow[tid] = grow;
    }
    __syncthreads();

    const int lr0 = tid >> 2, seg = tid & 3;
    const size_t aoff0 = (size_t)s_arow[lr0] * K + seg * 8;
    const size_t aoff1 = (size_t)s_arow[lr0 + 64] * K + seg * 8;
    const size_t boff0g = b_base + (size_t)(col0 + lr0) * K + seg * 8;
    const size_t boff1g = b_base + (size_t)(col0 + lr0 + 64) * K + seg * 8;
    const uint32_t so0 = (uint32_t)(lr0 * LDA + seg * 8) * 2;
    const uint32_t so1 = (uint32_t)((lr0 + 64) * LDA + seg * 8) * 2;

#define ISSUE_CHUNK(cc, ss) do {                                             \
        const int k0_ = (cc) << 5;                                           \
        const uint32_t sb_ = tb + (uint32_t)((ss) * NT * TILE_E) * 2;        \
        cpa16(sb_ + so0,              Ah + aoff0 + k0_);                     \
        cpa16(sb_ + so1,              Ah + aoff1 + k0_);                     \
        cpa16(sb_ + TILE_E * 2 + so0, Al + aoff0 + k0_);                     \
        cpa16(sb_ + TILE_E * 2 + so1, Al + aoff1 + k0_);                     \
        cpa16(sb_ + TILE_E * 4 + so0, Bh + boff0g + k0_);                    \
        cpa16(sb_ + TILE_E * 4 + so1, Bh + boff1g + k0_);                    \
        if (TERMS == 3) {                                                    \
            cpa16(sb_ + TILE_E * 6 + so0, Bl + boff0g + k0_);                \
            cpa16(sb_ + TILE_E * 6 + so1, Bl + boff1g + k0_);                \
        }                                                                    \
        asm volatile("cp.async.commit_group;" ::: "memory");                 \
    } while (0)

    float acc[4][4][4];
#pragma unroll
    for (int i = 0; i < 4; i++)
#pragma unroll
        for (int j = 0; j < 4; j++)
#pragma unroll
            for (int k = 0; k < 4; k++) acc[i][j][k] = 0.f;

    const uint32_t a_lm = (uint32_t)((warp_m * 64 + (lane & 15)) * LDA + (lane >> 4) * 8) * 2;
    const int brow = warp_n * 32 + ((lane >> 4) << 3) + (lane & 7);
    const uint32_t b_lm0 = (uint32_t)(brow * LDA + ((lane >> 3) & 1) * 8) * 2;
    const uint32_t b_lm1 = (uint32_t)((brow + 16) * LDA + ((lane >> 3) & 1) * 8) * 2;

    const int nch = K >> 5;
    ISSUE_CHUNK(0, 0);

    for (int c = 0; c < nch; c++) {
        const int cur = c & 1;
        if (c + 1 < nch) {
            ISSUE_CHUNK(c + 1, cur ^ 1);
            asm volatile("cp.async.wait_group 1;" ::: "memory");
        } else {
            asm volatile("cp.async.wait_group 0;" ::: "memory");
        }
        __syncthreads();

        const uint32_t uAh = tb + (uint32_t)((cur * NT + 0) * TILE_E) * 2;
        const uint32_t uAl = tb + (uint32_t)((cur * NT + 1) * TILE_E) * 2;
        const uint32_t uBh = tb + (uint32_t)((cur * NT + 2) * TILE_E) * 2;
        const uint32_t uBl = tb + (uint32_t)((cur * NT + 3) * TILE_E) * 2;

#pragma unroll
        for (int ks = 0; ks < 2; ks++) {
            const uint32_t kofs = (uint32_t)(ks * 16) * 2;
            uint32_t bh[4][2], bl[4][2];
            ldm_x4(bh[0][0], bh[0][1], bh[1][0], bh[1][1], uBh + b_lm0 + kofs);
            ldm_x4(bh[2][0], bh[2][1], bh[3][0], bh[3][1], uBh + b_lm1 + kofs);
            if (TERMS == 3) {
                ldm_x4(bl[0][0], bl[0][1], bl[1][0], bl[1][1], uBl + b_lm0 + kofs);
                ldm_x4(bl[2][0], bl[2][1], bl[3][0], bl[3][1], uBl + b_lm1 + kofs);
            }
#pragma unroll
            for (int am = 0; am < 4; am++) {
                uint32_t a[4];
                ldm_x4(a[0], a[1], a[2], a[3],
                       uAh + a_lm + kofs + (uint32_t)(am * 16 * LDA) * 2);
#pragma unroll
                for (int bn = 0; bn < 4; bn++) mma_bf16(acc[am][bn], a, bh[bn]);
                if (TERMS == 3) {
#pragma unroll
                    for (int bn = 0; bn < 4; bn++) mma_bf16(acc[am][bn], a, bl[bn]);
                }
            }
#pragma unroll
            for (int am = 0; am < 4; am++) {
                uint32_t a[4];
                ldm_x4(a[0], a[1], a[2], a[3],
                       uAl + a_lm + kofs + (uint32_t)(am * 16 * LDA) * 2);
#pragma unroll
                for (int bn = 0; bn < 4; bn++) mma_bf16(acc[am][bn], a, bh[bn]);
            }
        }
        __syncthreads();
    }
#undef ISSUE_CHUNK

    // ---- epilogue ----
#pragma unroll
    for (int am = 0; am < 4; am++) {
#pragma unroll
        for (int half = 0; half < 2; half++) {
            const int pos = row0 + warp_m * 64 + am * 16 + g + half * 8;
            if (AMODE && pos >= cnt) continue;
            const size_t rbase = AMODE ? ((size_t)e * T + pos) * (size_t)N
                                       : (size_t)pos * (size_t)N;
#pragma unroll
            for (int bn = 0; bn < 4; bn++) {
                const int cc = col0 + warp_n * 32 + bn * 8 + tg * 2;
                float v0 = acc[am][bn][half * 2 + 0];
                float v1 = acc[am][bn][half * 2 + 1];
                if (EPI == 2 || EPI == 3) {
                    const float2 s2 = *(const float2*)(scl + (size_t)e * N + cc);
                    v0 *= s2.x; v1 *= s2.y;
                }
                if (EPI == 1 || EPI == 3) {
                    const float2 g2 = *(const float2*)(G + rbase + cc);
                    v0 = silu_f(g2.x) * v0; v1 = silu_f(g2.y) * v1;
                    __nv_bfloat16 h0 = __float2bfloat16(v0), h1 = __float2bfloat16(v1);
                    *(__nv_bfloat162*)(Chi + rbase + cc) = __halves2bfloat162(h0, h1);
                    *(__nv_bfloat162*)(Clo + rbase + cc) = __halves2bfloat162(
                        __float2bfloat16(v0 - __bfloat162float(h0)),
                        __float2bfloat16(v1 - __bfloat162float(h1)));
                } else {
                    *(float2*)(Cf + rbase + cc) = make_float2(v0, v1);
                }
            }
        }
    }
}

// ---------------- final combine ---------------------------------------------
__global__ void combine_kernel(float* __restrict__ out) {
    int idx = blockIdx.x * blockDim.x + threadIdx.x;
    if (idx >= T * D / 4) return;
    int t = idx / (D / 4), d4 = idx % (D / 4);
    float cw0 = d_tok_w[t * 2 + 0], cw1 = d_tok_w[t * 2 + 1];
    int e0 = d_tok_e[t * 2 + 0], e1 = d_tok_e[t * 2 + 1];
    int p0 = d_tok_p[t * 2 + 0], p1 = d_tok_p[t * 2 + 1];
    float s = 1.f - cw0 - cw1;
    float4 a = ((const float4*)(d_shared + (size_t)t * D))[d4];
    float4 b = ((const float4*)(d_eo + ((size_t)e0 * T + p0) * D))[d4];
    float4 c = ((const float4*)(d_eo + ((size_t)e1 * T + p1) * D))[d4];
    float4 r;
    r.x = s * a.x + cw0 * b.x + cw1 * c.x;
    r.y = s * a.y + cw0 * b.y + cw1 * c.y;
    r.z = s * a.z + cw0 * b.z + cw1 * c.z;
    r.w = s * a.w + cw0 * b.w + cw1 * c.w;
    ((float4*)out)[(size_t)t * (D / 4) + d4] = r;
}

// ---------------- launch ----------------------------------------------------
#define SMEM3 (512 + 2 * 4 * 128 * LDA * 2)   // 82432
#define SMEM2 (512 + 2 * 3 * 128 * LDA * 2)   // 61952

extern "C" void kernel_launch(void* const* d_in, const int* in_sizes, int n_in,
                              void* d_out, int out_size) {
    const float *x, *rw, *sgw, *suw, *sdw, *gsc, *usc, *dsc, *alpha;
    const int *gq, *uq, *dq;
    bool dict_order = (n_in >= 12 && in_sizes[0] == T * D && in_sizes[1] == E * D &&
                       in_sizes[5] == E * DFE && in_sizes[8] == E);
    if (dict_order) {
        x = (const float*)d_in[0];  rw = (const float*)d_in[1];
        sgw = (const float*)d_in[2]; suw = (const float*)d_in[3];
        sdw = (const float*)d_in[4]; gsc = (const float*)d_in[5];
        usc = (const float*)d_in[6]; dsc = (const float*)d_in[7];
        alpha = (const float*)d_in[8];
        gq = (const int*)d_in[9]; uq = (const int*)d_in[10]; dq = (const int*)d_in[11];
    } else {
        alpha = (const float*)d_in[0];
        dq = (const int*)d_in[1];  dsc = (const float*)d_in[2];
        gq = (const int*)d_in[3];  gsc = (const float*)d_in[4];
        rw = (const float*)d_in[5];
        sdw = (const float*)d_in[6]; sgw = (const float*)d_in[7]; suw = (const float*)d_in[8];
        int o = (n_in >= 13 && in_sizes[9] == 1) ? 1 : 0;
        uq = (const int*)d_in[9 + o]; usc = (const float*)d_in[10 + o];
        x = (const float*)d_in[11 + o];
    }
    float* out = (float*)d_out;

    __nv_bfloat16 *p_xh, *p_xl, *p_hsh, *p_hsl, *p_heh, *p_hel, *p_gqb, *p_uqb, *p_dqb;
    __nv_bfloat16 *p_sgwh, *p_sgwl, *p_suwh, *p_suwl, *p_sdwh, *p_sdwl;
    float *p_gsv, *p_gev, *p_shared, *p_eo;
    cudaGetSymbolAddress((void**)&p_xh, d_xh);     cudaGetSymbolAddress((void**)&p_xl, d_xl);
    cudaGetSymbolAddress((void**)&p_sgwh, d_sgwh); cudaGetSymbolAddress((void**)&p_sgwl, d_sgwl);
    cudaGetSymbolAddress((void**)&p_suwh, d_suwh); cudaGetSymbolAddress((void**)&p_suwl, d_suwl);
    cudaGetSymbolAddress((void**)&p_sdwh, d_sdwh); cudaGetSymbolAddress((void**)&p_sdwl, d_sdwl);
    cudaGetSymbolAddress((void**)&p_hsh, d_hsh);   cudaGetSymbolAddress((void**)&p_hsl, d_hsl);
    cudaGetSymbolAddress((void**)&p_heh, d_heh);   cudaGetSymbolAddress((void**)&p_hel, d_hel);
    cudaGetSymbolAddress((void**)&p_gqb, d_gqb);   cudaGetSymbolAddress((void**)&p_uqb, d_uqb);
    cudaGetSymbolAddress((void**)&p_dqb, d_dqb);
    cudaGetSymbolAddress((void**)&p_gsv, d_gsv);   cudaGetSymbolAddress((void**)&p_gev, d_gev);
    cudaGetSymbolAddress((void**)&p_shared, d_shared);
    cudaGetSymbolAddress((void**)&p_eo, d_eo);

    cudaFuncSetAttribute(hmma_gemm<3, 0, 0>, cudaFuncAttributeMaxDynamicSharedMemorySize, SMEM3);
    cudaFuncSetAttribute(hmma_gemm<3, 0, 1>, cudaFuncAttributeMaxDynamicSharedMemorySize, SMEM3);
    cudaFuncSetAttribute(hmma_gemm<2, 1, 2>, cudaFuncAttributeMaxDynamicSharedMemorySize, SMEM2);
    cudaFuncSetAttribute(hmma_gemm<2, 1, 3>, cudaFuncAttributeMaxDynamicSharedMemorySize, SMEM2);
    cudaFuncSetAttribute(hmma_gemm<2, 2, 2>, cudaFuncAttributeMaxDynamicSharedMemorySize, SMEM2);

    // fused prologue: zero counts + 4 splits + 3 quant conversions (one launch)
    prologue_kernel<<<(PTOT + 255) / 256, 256>>>(x, sgw, suw, sdw, gq, uq, dq);
    router_kernel<<<T / 8, 256>>>(x, rw, alpha);

    // shared MLP (3-term, proven M128 config)
    hmma_gemm<3, 0, 0><<<dim3(DFS / 128, T / 128), 256, SMEM3>>>(
        p_xh, p_xl, p_sgwh, p_sgwl, nullptr, nullptr, p_gsv, nullptr, nullptr, DFS, D);
    hmma_gemm<3, 0, 1><<<dim3(DFS / 128, T / 128), 256, SMEM3>>>(
        p_xh, p_xl, p_suwh, p_suwl, nullptr, p_gsv, nullptr, p_hsh, p_hsl, DFS, D);
    hmma_gemm<3, 0, 0><<<dim3(D / 128, T / 128), 256, SMEM3>>>(
        p_hsh, p_hsl, p_sdwh, p_sdwl, nullptr, nullptr, p_shared, nullptr, nullptr, D, DFS);

    // routed experts (2-term, M128)
    hmma_gemm<2, 1, 2><<<dim3(DFE / 128, T / 128, E), 256, SMEM2>>>(
        p_xh, p_xl, p_gqb, nullptr, gsc, nullptr, p_gev, nullptr, nullptr, DFE, D);
    hmma_gemm<2, 1, 3><<<dim3(DFE / 128, T / 128, E), 256, SMEM2>>>(
        p_xh, p_xl, p_uqb, nullptr, usc, p_gev, nullptr, p_heh, p_hel, DFE, D);
    hmma_gemm<2, 2, 2><<<dim3(D / 128, T / 128, E), 256, SMEM2>>>(
        p_heh, p_hel, p_dqb, nullptr, dsc, nullptr, p_eo, nullptr, nullptr, D, DFE);

    combine_kernel<<<(T * D / 4 + 255) / 256, 256>>>(out);
}